// round 2
// baseline (speedup 1.0000x reference)
#include <cuda_runtime.h>
#include <cstdint>

#define NN 50000
#define EE 1600000
#define IN_C 128
#define HH 64
#define OUT_C 40
#define ALPHA 0.8f
#define LN_EPS 1e-5f

// Scratch (device globals; 16B-aligned via float4)
__device__ float4 g_xh4[NN * (HH / 4)];
__device__ float4 g_xU4[NN * (HH / 4)];
__device__ float4 g_h4 [NN * (HH / 4)];
__device__ float4 g_a4 [NN * (HH / 4)];
__device__ float4 g_z4 [NN * (HH / 4)];
__device__ int    g_row[EE];
__device__ int    g_col[EE];
__device__ int    g_is64;   // 1 if edge_index buffer is int64, 0 if int32

#define g_xh ((float*)g_xh4)
#define g_xU ((float*)g_xU4)
#define g_h  ((float*)g_h4)
#define g_a  ((float*)g_a4)
#define g_z  ((float*)g_z4)

__device__ __forceinline__ float fast_tanh(float x) {
    float e = __expf(2.0f * x);
    return 1.0f - __fdividef(2.0f, e + 1.0f);
}

// ---------------------------------------------------------------------------
// Probe: detect int64 vs int32 edge_index. If int64 (values < 2^31, LE),
// every odd 32-bit word of the first 128 words is zero.
// ---------------------------------------------------------------------------
__global__ void k_probe(const int* __restrict__ ei_raw) {
    if (threadIdx.x == 0 && blockIdx.x == 0) {
        int allzero = 1;
        #pragma unroll
        for (int i = 1; i < 128; i += 2) allzero &= (ei_raw[i] == 0);
        g_is64 = allzero;
    }
}

__global__ __launch_bounds__(256) void k_convert(const int* __restrict__ ei_raw) {
    int e = blockIdx.x * blockDim.x + threadIdx.x;
    if (e >= EE) return;
    if (g_is64) {
        const long long* p = (const long long*)ei_raw;
        g_row[e] = (int)p[e];
        g_col[e] = (int)p[EE + e];
    } else {
        g_row[e] = ei_raw[e];
        g_col[e] = ei_raw[EE + e];
    }
}

// ---------------------------------------------------------------------------
// P1: xh = x @ We^T + be       [N,128] @ [128,64]
// ---------------------------------------------------------------------------
__global__ __launch_bounds__(256) void k_extract(const float* __restrict__ x,
                                                 const float* __restrict__ We,
                                                 const float* __restrict__ be) {
    __shared__ float Wet[IN_C * HH];   // Wet[k*64 + c] = We[c*128 + k]
    __shared__ float xs[4][IN_C];
    int tid = threadIdx.x;
    int c = tid & 63, y = tid >> 6;
    for (int idx = tid; idx < IN_C * HH; idx += 256) {
        int cc = idx >> 7, k = idx & 127;
        Wet[k * HH + cc] = We[idx];
    }
    int i = blockIdx.x * 4 + y;
    if (i < NN) {
        xs[y][c]      = x[i * IN_C + c];
        xs[y][c + 64] = x[i * IN_C + c + 64];
    }
    __syncthreads();
    if (i < NN) {
        float acc = be[c];
        #pragma unroll
        for (int k = 0; k < IN_C; k++) acc += xs[y][k] * Wet[k * HH + c];
        g_xh[i * HH + c] = acc;
    }
}

// ---------------------------------------------------------------------------
// P2: xU = deg * (xh @ U^T + bU);  z = 0
// ---------------------------------------------------------------------------
__global__ __launch_bounds__(256) void k_xu(const float* __restrict__ nf,
                                            const float* __restrict__ U,
                                            const float* __restrict__ bU) {
    __shared__ float Ut[HH * HH];      // Ut[k*64 + c] = U[c*64 + k]
    __shared__ float xhs[4][HH];
    int tid = threadIdx.x;
    int c = tid & 63, y = tid >> 6;
    for (int idx = tid; idx < HH * HH; idx += 256) {
        int cc = idx >> 6, k = idx & 63;
        Ut[k * HH + cc] = U[idx];
    }
    int i = blockIdx.x * 4 + y;
    if (i < NN) xhs[y][c] = g_xh[i * HH + c];
    __syncthreads();
    if (i < NN) {
        float nfv = nf[i];
        float deg = 1.0f / nfv;
        if (isinf(deg)) deg = 0.0f;
        float acc = bU[c];
        #pragma unroll
        for (int k = 0; k < HH; k++) acc += xhs[y][k] * Ut[k * HH + c];
        g_xU[i * HH + c] = deg * acc;
        g_z[i * HH + c]  = 0.0f;
    }
}

// ---------------------------------------------------------------------------
// A: h = nf * (z @ W^T + xU);  a = 0
// ---------------------------------------------------------------------------
__global__ __launch_bounds__(256) void k_preh(const float* __restrict__ nf,
                                              const float* __restrict__ W) {
    __shared__ float Wt[HH * HH];      // Wt[k*64 + c] = W[c*64 + k]
    __shared__ float zs[4][HH];
    int tid = threadIdx.x;
    int c = tid & 63, y = tid >> 6;
    for (int idx = tid; idx < HH * HH; idx += 256) {
        int cc = idx >> 6, k = idx & 63;
        Wt[k * HH + cc] = W[idx];
    }
    int i = blockIdx.x * 4 + y;
    if (i < NN) zs[y][c] = g_z[i * HH + c];
    __syncthreads();
    if (i < NN) {
        float acc = 0.0f;
        #pragma unroll
        for (int k = 0; k < HH; k++) acc += zs[y][k] * Wt[k * HH + c];
        g_h[i * HH + c] = nf[i] * (acc + g_xU[i * HH + c]);
        g_a[i * HH + c] = 0.0f;
    }
}

// ---------------------------------------------------------------------------
// B: edge kernel. Half-warp (16 lanes x float4 = 64 ch) per edge.
// ---------------------------------------------------------------------------
__global__ __launch_bounds__(256) void k_edge(const float* __restrict__ nf,
                                              const float* __restrict__ gamma,
                                              const float* __restrict__ beta) {
    int tid = blockIdx.x * blockDim.x + threadIdx.x;
    int l = threadIdx.x & 15;
    int hw = tid >> 4;
    int nhw = (gridDim.x * blockDim.x) >> 4;
    unsigned hmask = 0xFFFFu << (threadIdx.x & 16);

    const float4 gm = *(const float4*)(gamma + 4 * l);
    const float4 bt = *(const float4*)(beta + 4 * l);

    for (int e = hw; e < EE; e += nhw) {
        int r  = g_row[e];
        int cn = g_col[e];
        const float4 hr = g_h4[r  * 16 + l];
        const float4 hc = g_h4[cn * 16 + l];

        float t0 = fast_tanh(hr.x - hc.x);
        float t1 = fast_tanh(hr.y - hc.y);
        float t2 = fast_tanh(hr.z - hc.z);
        float t3 = fast_tanh(hr.w - hc.w);

        float s  = t0 + t1 + t2 + t3;
        float s2 = t0 * t0 + t1 * t1 + t2 * t2 + t3 * t3;
        #pragma unroll
        for (int m = 8; m; m >>= 1) {
            s  += __shfl_xor_sync(hmask, s,  m);
            s2 += __shfl_xor_sync(hmask, s2, m);
        }
        float mean = s * (1.0f / 64.0f);
        float var  = s2 * (1.0f / 64.0f) - mean * mean;
        float rstd = rsqrtf(var + LN_EPS);

        float m0 = gm.x * ((t0 - mean) * rstd) + bt.x;
        float m1 = gm.y * ((t1 - mean) * rstd) + bt.y;
        float m2 = gm.z * ((t2 - mean) * rstd) + bt.z;
        float m3 = gm.w * ((t3 - mean) * rstd) + bt.w;

        float nfr = nf[r];
        float nfc = nf[cn];
        float* ar = (float*)(g_a4 + r  * 16 + l);
        float* ac = (float*)(g_a4 + cn * 16 + l);
        asm volatile("red.global.add.v4.f32 [%0], {%1,%2,%3,%4};"
                     :: "l"(ar), "f"(m0 * nfr), "f"(m1 * nfr), "f"(m2 * nfr), "f"(m3 * nfr)
                     : "memory");
        asm volatile("red.global.add.v4.f32 [%0], {%1,%2,%3,%4};"
                     :: "l"(ac), "f"(-m0 * nfc), "f"(-m1 * nfc), "f"(-m2 * nfc), "f"(-m3 * nfc)
                     : "memory");
    }
}

// ---------------------------------------------------------------------------
// C: z = ALPHA * (-(a @ W)) + (1-ALPHA) * z
// ---------------------------------------------------------------------------
__global__ __launch_bounds__(256) void k_update(const float* __restrict__ W) {
    __shared__ float Ws[HH * HH];
    __shared__ float as[4][HH];
    int tid = threadIdx.x;
    int c = tid & 63, y = tid >> 6;
    for (int idx = tid; idx < HH * HH; idx += 256) Ws[idx] = W[idx];
    int i = blockIdx.x * 4 + y;
    if (i < NN) as[y][c] = g_a[i * HH + c];
    __syncthreads();
    if (i < NN) {
        float acc = 0.0f;
        #pragma unroll
        for (int k = 0; k < HH; k++) acc += as[y][k] * Ws[k * HH + c];
        g_z[i * HH + c] = ALPHA * (-acc) + (1.0f - ALPHA) * g_z[i * HH + c];
    }
}

// ---------------------------------------------------------------------------
// D: out = (nf*z + xh) @ Wlast^T + blast     [N,64] @ [64,40]
// ---------------------------------------------------------------------------
__global__ __launch_bounds__(256) void k_out(const float* __restrict__ nf,
                                             const float* __restrict__ Wl,
                                             const float* __restrict__ bl,
                                             float* __restrict__ out) {
    __shared__ float Wlt[HH * OUT_C];
    __shared__ float sv[4][HH];
    int tid = threadIdx.x;
    int c = tid & 63, y = tid >> 6;
    for (int idx = tid; idx < HH * OUT_C; idx += 256) {
        int o = idx >> 6, k = idx & 63;
        Wlt[k * OUT_C + o] = Wl[idx];
    }
    int i = blockIdx.x * 4 + y;
    if (i < NN) sv[y][c] = nf[i] * g_z[i * HH + c] + g_xh[i * HH + c];
    __syncthreads();
    if (i < NN && c < OUT_C) {
        float acc = bl[c];
        #pragma unroll
        for (int k = 0; k < HH; k++) acc += sv[y][k] * Wlt[k * OUT_C + c];
        out[i * OUT_C + c] = acc;
    }
}

// ---------------------------------------------------------------------------
extern "C" void kernel_launch(void* const* d_in, const int* in_sizes, int n_in,
                              void* d_out, int out_size) {
    const float* x     = (const float*)d_in[0];
    const int*   eiRaw = (const int*)d_in[1];
    const float* nf    = (const float*)d_in[2];
    const float* We    = (const float*)d_in[3];
    const float* be    = (const float*)d_in[4];
    const float* W     = (const float*)d_in[5];
    const float* U     = (const float*)d_in[6];
    const float* bU    = (const float*)d_in[7];
    const float* gamma = (const float*)d_in[8];
    const float* beta  = (const float*)d_in[9];
    const float* Wl    = (const float*)d_in[10];
    const float* bl    = (const float*)d_in[11];
    float* out = (float*)d_out;

    k_probe<<<1, 32>>>(eiRaw);
    k_convert<<<(EE + 255) / 256, 256>>>(eiRaw);

    int nodeBlocks = (NN + 3) / 4;
    k_extract<<<nodeBlocks, 256>>>(x, We, be);
    k_xu<<<nodeBlocks, 256>>>(nf, U, bU);

    for (int s = 0; s < 4; s++) {
        k_preh<<<nodeBlocks, 256>>>(nf, W);
        k_edge<<<1184, 256>>>(nf, gamma, beta);
        k_update<<<nodeBlocks, 256>>>(W);
    }

    k_out<<<nodeBlocks, 256>>>(nf, Wl, bl, out);
}

// round 3
// speedup vs baseline: 2.4112x; 2.4112x over previous
#include <cuda_runtime.h>
#include <cstdint>

#define NN 50000
#define EE 1600000
#define IN_C 128
#define HH 64
#define OUT_C 40
#define ALPHA 0.8f
#define LN_EPS 1e-5f

// Scratch (device globals; 16B-aligned via float4)
__device__ float4 g_xh4[NN * 16];
__device__ float4 g_xU4[NN * 16];
__device__ float4 g_h4 [NN * 16];
__device__ float4 g_a4 [NN * 16];
__device__ float4 g_z4 [NN * 16];
__device__ int    g_row[EE];
__device__ int    g_col[EE];
__device__ int    g_is64;
// pre-transposed weights
__device__ float  g_WeT[IN_C * HH];   // [k][c] = We[c][k]
__device__ float  g_UT [HH * HH];     // [k][c] = U[c][k]
__device__ float  g_WT [HH * HH];     // [k][c] = W[c][k]

#define g_xh ((float*)g_xh4)
#define g_a  ((float*)g_a4)

__device__ __forceinline__ float htanh(float x) {
    float y;
    asm("tanh.approx.f32 %0, %1;" : "=f"(y) : "f"(x));
    return y;
}

// ---------------------------------------------------------------------------
__global__ void k_probe(const int* __restrict__ ei_raw) {
    if (threadIdx.x == 0 && blockIdx.x == 0) {
        int allzero = 1;
        #pragma unroll
        for (int i = 1; i < 128; i += 2) allzero &= (ei_raw[i] == 0);
        g_is64 = allzero;
    }
}

__global__ __launch_bounds__(256) void k_convert(const int* __restrict__ ei_raw) {
    int e = blockIdx.x * blockDim.x + threadIdx.x;
    if (e >= EE) return;
    if (g_is64) {
        const long long* p = (const long long*)ei_raw;
        g_row[e] = (int)p[e];
        g_col[e] = (int)p[EE + e];
    } else {
        g_row[e] = ei_raw[e];
        g_col[e] = ei_raw[EE + e];
    }
}

// ---------------------------------------------------------------------------
// Transpose weights once (coalesced-enough; tiny)
// ---------------------------------------------------------------------------
__global__ __launch_bounds__(256) void k_prep(const float* __restrict__ We,
                                              const float* __restrict__ U,
                                              const float* __restrict__ W) {
    int idx = blockIdx.x * blockDim.x + threadIdx.x;
    if (idx < IN_C * HH) {
        int k = idx >> 6, c = idx & 63;
        g_WeT[idx] = We[c * IN_C + k];
    }
    if (idx < HH * HH) {
        int k = idx >> 6, c = idx & 63;
        g_UT[idx] = U[c * HH + k];
        g_WT[idx] = W[c * HH + k];
    }
}

// ---------------------------------------------------------------------------
// Front: xh = x@We^T + be ; xU = deg*(xh@U^T + bU) ; h0 = nf*xU ; z=0 ; a=0
// 64 nodes/block, 256 threads. thread: 2 nodes x 8 channels.
// dyn smem: Xs[64*129] | Wes[128*64] | Uts[64*64]
// ---------------------------------------------------------------------------
__global__ __launch_bounds__(256) void k_front(const float* __restrict__ x,
                                               const float* __restrict__ be,
                                               const float* __restrict__ bU,
                                               const float* __restrict__ nf) {
    extern __shared__ float sm[];
    float* Xs  = sm;                 // 64 * 129
    float* Wes = sm + 64 * 129;      // 128 * 64
    float* Uts = Wes + IN_C * HH;    // 64 * 64

    int tid = threadIdx.x;
    int g = tid & 7, nb = tid >> 3;
    int base = blockIdx.x * 64;

    for (int idx = tid; idx < 64 * IN_C; idx += 256) {
        int n = idx >> 7, k = idx & 127;
        Xs[n * 129 + k] = (base + n < NN) ? x[(base + n) * IN_C + k] : 0.0f;
    }
    for (int idx = tid; idx < IN_C * HH; idx += 256) Wes[idx] = g_WeT[idx];
    for (int idx = tid; idx < HH * HH; idx += 256)  Uts[idx] = g_UT[idx];
    __syncthreads();

    const float4* Wes4 = (const float4*)Wes;
    const float4* Uts4 = (const float4*)Uts;
    float4 beA = ((const float4*)be)[2 * g], beB = ((const float4*)be)[2 * g + 1];
    float4 bUA = ((const float4*)bU)[2 * g], bUB = ((const float4*)bU)[2 * g + 1];

    float4 a0A = {0,0,0,0}, a0B = {0,0,0,0}, a1A = {0,0,0,0}, a1B = {0,0,0,0};
    #pragma unroll 8
    for (int k = 0; k < IN_C; k++) {
        float v0 = Xs[nb * 129 + k];
        float v1 = Xs[(nb + 32) * 129 + k];
        float4 w0 = Wes4[k * 16 + 2 * g];
        float4 w1 = Wes4[k * 16 + 2 * g + 1];
        a0A.x += v0 * w0.x; a0A.y += v0 * w0.y; a0A.z += v0 * w0.z; a0A.w += v0 * w0.w;
        a0B.x += v0 * w1.x; a0B.y += v0 * w1.y; a0B.z += v0 * w1.z; a0B.w += v0 * w1.w;
        a1A.x += v1 * w0.x; a1A.y += v1 * w0.y; a1A.z += v1 * w0.z; a1A.w += v1 * w0.w;
        a1B.x += v1 * w1.x; a1B.y += v1 * w1.y; a1B.z += v1 * w1.z; a1B.w += v1 * w1.w;
    }
    a0A.x += beA.x; a0A.y += beA.y; a0A.z += beA.z; a0A.w += beA.w;
    a0B.x += beB.x; a0B.y += beB.y; a0B.z += beB.z; a0B.w += beB.w;
    a1A.x += beA.x; a1A.y += beA.y; a1A.z += beA.z; a1A.w += beA.w;
    a1B.x += beB.x; a1B.y += beB.y; a1B.z += beB.z; a1B.w += beB.w;

    int gn0 = base + nb, gn1 = base + nb + 32;
    if (gn0 < NN) { g_xh4[gn0 * 16 + 2 * g] = a0A; g_xh4[gn0 * 16 + 2 * g + 1] = a0B; }
    if (gn1 < NN) { g_xh4[gn1 * 16 + 2 * g] = a1A; g_xh4[gn1 * 16 + 2 * g + 1] = a1B; }

    __syncthreads();
    // stash xh into Xs for phase 2
    float* r0 = Xs + nb * 129 + 8 * g;
    float* r1 = Xs + (nb + 32) * 129 + 8 * g;
    r0[0]=a0A.x; r0[1]=a0A.y; r0[2]=a0A.z; r0[3]=a0A.w; r0[4]=a0B.x; r0[5]=a0B.y; r0[6]=a0B.z; r0[7]=a0B.w;
    r1[0]=a1A.x; r1[1]=a1A.y; r1[2]=a1A.z; r1[3]=a1A.w; r1[4]=a1B.x; r1[5]=a1B.y; r1[6]=a1B.z; r1[7]=a1B.w;
    __syncthreads();

    float4 c0A = {0,0,0,0}, c0B = {0,0,0,0}, c1A = {0,0,0,0}, c1B = {0,0,0,0};
    #pragma unroll 8
    for (int k = 0; k < HH; k++) {
        float v0 = Xs[nb * 129 + k];
        float v1 = Xs[(nb + 32) * 129 + k];
        float4 w0 = Uts4[k * 16 + 2 * g];
        float4 w1 = Uts4[k * 16 + 2 * g + 1];
        c0A.x += v0 * w0.x; c0A.y += v0 * w0.y; c0A.z += v0 * w0.z; c0A.w += v0 * w0.w;
        c0B.x += v0 * w1.x; c0B.y += v0 * w1.y; c0B.z += v0 * w1.z; c0B.w += v0 * w1.w;
        c1A.x += v1 * w0.x; c1A.y += v1 * w0.y; c1A.z += v1 * w0.z; c1A.w += v1 * w0.w;
        c1B.x += v1 * w1.x; c1B.y += v1 * w1.y; c1B.z += v1 * w1.z; c1B.w += v1 * w1.w;
    }
    float4 z4 = {0,0,0,0};
    #pragma unroll
    for (int j = 0; j < 2; j++) {
        int gn = (j == 0) ? gn0 : gn1;
        if (gn >= NN) continue;
        float nfv = nf[gn];
        float deg = 1.0f / nfv;
        if (isinf(deg)) deg = 0.0f;
        float4 cA = (j == 0) ? c0A : c1A;
        float4 cB = (j == 0) ? c0B : c1B;
        float4 xuA, xuB, hA, hB;
        xuA.x = deg * (cA.x + bUA.x); xuA.y = deg * (cA.y + bUA.y);
        xuA.z = deg * (cA.z + bUA.z); xuA.w = deg * (cA.w + bUA.w);
        xuB.x = deg * (cB.x + bUB.x); xuB.y = deg * (cB.y + bUB.y);
        xuB.z = deg * (cB.z + bUB.z); xuB.w = deg * (cB.w + bUB.w);
        hA.x = nfv * xuA.x; hA.y = nfv * xuA.y; hA.z = nfv * xuA.z; hA.w = nfv * xuA.w;
        hB.x = nfv * xuB.x; hB.y = nfv * xuB.y; hB.z = nfv * xuB.z; hB.w = nfv * xuB.w;
        g_xU4[gn * 16 + 2 * g] = xuA; g_xU4[gn * 16 + 2 * g + 1] = xuB;
        g_h4 [gn * 16 + 2 * g] = hA;  g_h4 [gn * 16 + 2 * g + 1] = hB;
        g_z4 [gn * 16 + 2 * g] = z4;  g_z4 [gn * 16 + 2 * g + 1] = z4;
        g_a4 [gn * 16 + 2 * g] = z4;  g_a4 [gn * 16 + 2 * g + 1] = z4;
    }
}

// ---------------------------------------------------------------------------
// Edge: m = LN(tanh(h[r]-h[c])); a[r] += m*nf[r]; a[c] -= m*nf[c]
// ---------------------------------------------------------------------------
__global__ __launch_bounds__(256) void k_edge(const float* __restrict__ nf,
                                              const float* __restrict__ gamma,
                                              const float* __restrict__ beta) {
    int tid = blockIdx.x * blockDim.x + threadIdx.x;
    int l = threadIdx.x & 15;
    int hw = tid >> 4;
    int nhw = (gridDim.x * blockDim.x) >> 4;
    unsigned hmask = 0xFFFFu << (threadIdx.x & 16);

    const float4 gm = *(const float4*)(gamma + 4 * l);
    const float4 bt = *(const float4*)(beta + 4 * l);

    for (int e = hw; e < EE; e += nhw) {
        int r  = g_row[e];
        int cn = g_col[e];
        const float4 hr = g_h4[r  * 16 + l];
        const float4 hc = g_h4[cn * 16 + l];

        float t0 = htanh(hr.x - hc.x);
        float t1 = htanh(hr.y - hc.y);
        float t2 = htanh(hr.z - hc.z);
        float t3 = htanh(hr.w - hc.w);

        float s  = t0 + t1 + t2 + t3;
        float s2 = t0 * t0 + t1 * t1 + t2 * t2 + t3 * t3;
        #pragma unroll
        for (int m = 8; m; m >>= 1) {
            s  += __shfl_xor_sync(hmask, s,  m);
            s2 += __shfl_xor_sync(hmask, s2, m);
        }
        float mean = s * (1.0f / 64.0f);
        float var  = s2 * (1.0f / 64.0f) - mean * mean;
        float rstd = rsqrtf(var + LN_EPS);

        float m0 = gm.x * ((t0 - mean) * rstd) + bt.x;
        float m1 = gm.y * ((t1 - mean) * rstd) + bt.y;
        float m2 = gm.z * ((t2 - mean) * rstd) + bt.z;
        float m3 = gm.w * ((t3 - mean) * rstd) + bt.w;

        float nfr = nf[r];
        float nfc = nf[cn];
        float* ar = (float*)(g_a4 + r  * 16 + l);
        float* ac = (float*)(g_a4 + cn * 16 + l);
        asm volatile("red.global.add.v4.f32 [%0], {%1,%2,%3,%4};"
                     :: "l"(ar), "f"(m0 * nfr), "f"(m1 * nfr), "f"(m2 * nfr), "f"(m3 * nfr)
                     : "memory");
        asm volatile("red.global.add.v4.f32 [%0], {%1,%2,%3,%4};"
                     :: "l"(ac), "f"(-m0 * nfc), "f"(-m1 * nfc), "f"(-m2 * nfc), "f"(-m3 * nfc)
                     : "memory");
    }
}

// ---------------------------------------------------------------------------
// Fused step: t = a@W ; z = -ALPHA*t + (1-ALPHA)*z ; h = nf*(z@W^T + xU) ; a = 0
// 128 nodes/block, 256 threads. thread: 4 nodes x 8 channels.
// dyn smem: As[128*65] | Ws[64*64] | Wts[64*64]
// ---------------------------------------------------------------------------
__global__ __launch_bounds__(256) void k_fused(const float* __restrict__ W,
                                               const float* __restrict__ nf,
                                               int compute_h) {
    extern __shared__ float sm[];
    float* As  = sm;               // 128 * 65
    float* Ws  = sm + 128 * 65;    // 64 * 64 (as stored)
    float* Wts = Ws + HH * HH;     // 64 * 64 (transposed)

    int tid = threadIdx.x;
    int g = tid & 7, nb = tid >> 3;
    int base = blockIdx.x * 128;

    for (int idx = tid; idx < 128 * HH; idx += 256) {
        int n = idx >> 6, c = idx & 63;
        As[n * 65 + c] = (base + n < NN) ? g_a[(base + n) * HH + c] : 0.0f;
    }
    for (int idx = tid; idx < HH * HH; idx += 256) { Ws[idx] = W[idx]; Wts[idx] = g_WT[idx]; }
    __syncthreads();

    const float4* Ws4  = (const float4*)Ws;
    const float4* Wts4 = (const float4*)Wts;

    float4 tA[4], tB[4];
    #pragma unroll
    for (int j = 0; j < 4; j++) { tA[j] = make_float4(0,0,0,0); tB[j] = make_float4(0,0,0,0); }

    #pragma unroll 8
    for (int k = 0; k < HH; k++) {
        float4 w0 = Ws4[k * 16 + 2 * g];
        float4 w1 = Ws4[k * 16 + 2 * g + 1];
        #pragma unroll
        for (int j = 0; j < 4; j++) {
            float v = As[(nb + 32 * j) * 65 + k];
            tA[j].x += v * w0.x; tA[j].y += v * w0.y; tA[j].z += v * w0.z; tA[j].w += v * w0.w;
            tB[j].x += v * w1.x; tB[j].y += v * w1.y; tB[j].z += v * w1.z; tB[j].w += v * w1.w;
        }
    }

    // z update
    float4 znA[4], znB[4];
    #pragma unroll
    for (int j = 0; j < 4; j++) {
        int gn = base + nb + 32 * j;
        if (gn >= NN) { znA[j] = make_float4(0,0,0,0); znB[j] = make_float4(0,0,0,0); continue; }
        float4 zA = g_z4[gn * 16 + 2 * g], zB = g_z4[gn * 16 + 2 * g + 1];
        znA[j].x = -ALPHA * tA[j].x + (1.0f - ALPHA) * zA.x;
        znA[j].y = -ALPHA * tA[j].y + (1.0f - ALPHA) * zA.y;
        znA[j].z = -ALPHA * tA[j].z + (1.0f - ALPHA) * zA.z;
        znA[j].w = -ALPHA * tA[j].w + (1.0f - ALPHA) * zA.w;
        znB[j].x = -ALPHA * tB[j].x + (1.0f - ALPHA) * zB.x;
        znB[j].y = -ALPHA * tB[j].y + (1.0f - ALPHA) * zB.y;
        znB[j].z = -ALPHA * tB[j].z + (1.0f - ALPHA) * zB.z;
        znB[j].w = -ALPHA * tB[j].w + (1.0f - ALPHA) * zB.w;
        g_z4[gn * 16 + 2 * g] = znA[j];
        g_z4[gn * 16 + 2 * g + 1] = znB[j];
    }

    __syncthreads();
    #pragma unroll
    for (int j = 0; j < 4; j++) {
        float* rr = As + (nb + 32 * j) * 65 + 8 * g;
        rr[0]=znA[j].x; rr[1]=znA[j].y; rr[2]=znA[j].z; rr[3]=znA[j].w;
        rr[4]=znB[j].x; rr[5]=znB[j].y; rr[6]=znB[j].z; rr[7]=znB[j].w;
    }
    __syncthreads();

    if (compute_h) {
        #pragma unroll
        for (int j = 0; j < 4; j++) { tA[j] = make_float4(0,0,0,0); tB[j] = make_float4(0,0,0,0); }
        #pragma unroll 8
        for (int k = 0; k < HH; k++) {
            float4 w0 = Wts4[k * 16 + 2 * g];
            float4 w1 = Wts4[k * 16 + 2 * g + 1];
            #pragma unroll
            for (int j = 0; j < 4; j++) {
                float v = As[(nb + 32 * j) * 65 + k];
                tA[j].x += v * w0.x; tA[j].y += v * w0.y; tA[j].z += v * w0.z; tA[j].w += v * w0.w;
                tB[j].x += v * w1.x; tB[j].y += v * w1.y; tB[j].z += v * w1.z; tB[j].w += v * w1.w;
            }
        }
        #pragma unroll
        for (int j = 0; j < 4; j++) {
            int gn = base + nb + 32 * j;
            if (gn >= NN) continue;
            float nfv = nf[gn];
            float4 xuA = g_xU4[gn * 16 + 2 * g], xuB = g_xU4[gn * 16 + 2 * g + 1];
            float4 hA, hB;
            hA.x = nfv * (tA[j].x + xuA.x); hA.y = nfv * (tA[j].y + xuA.y);
            hA.z = nfv * (tA[j].z + xuA.z); hA.w = nfv * (tA[j].w + xuA.w);
            hB.x = nfv * (tB[j].x + xuB.x); hB.y = nfv * (tB[j].y + xuB.y);
            hB.z = nfv * (tB[j].z + xuB.z); hB.w = nfv * (tB[j].w + xuB.w);
            g_h4[gn * 16 + 2 * g] = hA;
            g_h4[gn * 16 + 2 * g + 1] = hB;
        }
    }

    float4 zero4 = make_float4(0,0,0,0);
    #pragma unroll
    for (int j = 0; j < 4; j++) {
        int gn = base + nb + 32 * j;
        if (gn >= NN) continue;
        g_a4[gn * 16 + 2 * g] = zero4;
        g_a4[gn * 16 + 2 * g + 1] = zero4;
    }
}

// ---------------------------------------------------------------------------
// Out: out = (nf*z + xh) @ Wlast^T + blast
// ---------------------------------------------------------------------------
__global__ __launch_bounds__(256) void k_out(const float* __restrict__ nf,
                                             const float* __restrict__ Wl,
                                             const float* __restrict__ bl,
                                             float* __restrict__ out) {
    __shared__ float Wlt[HH * OUT_C];
    __shared__ float sv[4][HH];
    int tid = threadIdx.x;
    int c = tid & 63, y = tid >> 6;
    for (int idx = tid; idx < HH * OUT_C; idx += 256) {
        int o = idx >> 6, k = idx & 63;
        Wlt[k * OUT_C + o] = Wl[idx];
    }
    int i = blockIdx.x * 4 + y;
    if (i < NN) sv[y][c] = nf[i] * ((float*)g_z4)[i * HH + c] + g_xh[i * HH + c];
    __syncthreads();
    if (i < NN && c < OUT_C) {
        float acc = bl[c];
        #pragma unroll
        for (int k = 0; k < HH; k++) acc += sv[y][k] * Wlt[k * OUT_C + c];
        out[i * OUT_C + c] = acc;
    }
}

// ---------------------------------------------------------------------------
extern "C" void kernel_launch(void* const* d_in, const int* in_sizes, int n_in,
                              void* d_out, int out_size) {
    const float* x     = (const float*)d_in[0];
    const int*   eiRaw = (const int*)d_in[1];
    const float* nf    = (const float*)d_in[2];
    const float* We    = (const float*)d_in[3];
    const float* be    = (const float*)d_in[4];
    const float* W     = (const float*)d_in[5];
    const float* U     = (const float*)d_in[6];
    const float* bU    = (const float*)d_in[7];
    const float* gamma = (const float*)d_in[8];
    const float* beta  = (const float*)d_in[9];
    const float* Wl    = (const float*)d_in[10];
    const float* bl    = (const float*)d_in[11];
    float* out = (float*)d_out;

    static int attr_done = 0;
    size_t front_smem = (64 * 129 + IN_C * HH + HH * HH) * sizeof(float);
    size_t fused_smem = (128 * 65 + 2 * HH * HH) * sizeof(float);
    if (!attr_done) {
        cudaFuncSetAttribute(k_front, cudaFuncAttributeMaxDynamicSharedMemorySize, (int)front_smem);
        cudaFuncSetAttribute(k_fused, cudaFuncAttributeMaxDynamicSharedMemorySize, (int)fused_smem);
        attr_done = 1;
    }

    k_probe<<<1, 32>>>(eiRaw);
    k_convert<<<(EE + 255) / 256, 256>>>(eiRaw);
    k_prep<<<(IN_C * HH + 255) / 256, 256>>>(We, U, W);
    k_front<<<(NN + 63) / 64, 256, front_smem>>>(x, be, bU, nf);

    for (int s = 0; s < 4; s++) {
        k_edge<<<1184, 256>>>(nf, gamma, beta);
        k_fused<<<(NN + 127) / 128, 256, fused_smem>>>(W, nf, s < 3 ? 1 : 0);
    }

    k_out<<<(NN + 3) / 4, 256>>>(nf, Wl, bl, out);
}